// round 9
// baseline (speedup 1.0000x reference)
#include <cuda_runtime.h>
#include <cuda_fp16.h>

#define NN 50000
#define EE 800000
#define D  128
#define G  8
#define C  10

// ---------------- scratch (static device globals; no allocs allowed) --------
__device__ float  g_out_isqrt[NN];
__device__ float  g_in_isqrt[NN];
__device__ __half g_h16A[NN * D];
__device__ __half g_h16B[NN * D];
__device__ __half g_W1hi[D * D];
__device__ __half g_W1lo[D * D];
__device__ __half g_W2hi[D * D];
__device__ __half g_W2lo[D * D];
__device__ float  g_sums[G * D];
__device__ int    g_outcnt[NN];
__device__ int    g_incnt[NN];
__device__ int    g_rowptr[NN + 1];
__device__ int    g_cursor[NN];
__device__ int    g_csr[EE];
__device__ int    g_bsums[256];

// ---------------- setup: zero degree arrays + pool sums, convert weights ------
__global__ __launch_bounds__(256)
void k_setup(int* __restrict__ outc, int* __restrict__ inc, int n,
             float* __restrict__ sums,
             const float* __restrict__ W1, const float* __restrict__ W2,
             __half* __restrict__ w1h, __half* __restrict__ w1l,
             __half* __restrict__ w2h, __half* __restrict__ w2l) {
    int i = blockIdx.x * 256 + threadIdx.x;
    if (i < n) { outc[i] = 0; inc[i] = 0; }
    if (i < G * D) sums[i] = 0.0f;
    if (i < D * D) {
        int k = i >> 7, nn = i & 127;
        float v = W1[i];
        __half hi = __float2half_rn(v);
        w1h[nn * D + k] = hi;
        w1l[nn * D + k] = __float2half_rn(v - __half2float(hi));
        v = W2[i];
        hi = __float2half_rn(v);
        w2h[nn * D + k] = hi;
        w2l[nn * D + k] = __float2half_rn(v - __half2float(hi));
    }
}

// ---------------- degree histograms (int) ------------------------------------
__global__ void k_degcount(const int* __restrict__ ei, int E,
                           int* __restrict__ outc, int* __restrict__ inc) {
    int e = blockIdx.x * blockDim.x + threadIdx.x;
    if (e < E) {
        atomicAdd(&outc[ei[e]], 1);
        atomicAdd(&inc[ei[E + e]], 1);
    }
}

// ---------------- scan helpers -------------------------------------------------
__device__ __forceinline__ int warp_incl_scan(int v, int lane) {
#pragma unroll
    for (int o = 1; o < 32; o <<= 1) {
        int t = __shfl_up_sync(0xffffffffu, v, o);
        if (lane >= o) v += t;
    }
    return v;
}

__device__ __forceinline__ int block_incl_scan(int v, int tid, int* ws) {
    int lane = tid & 31, wid = tid >> 5;
    int s = warp_incl_scan(v, lane);
    if (lane == 31) ws[wid] = s;
    __syncthreads();
    if (wid == 0) {
        int t = (lane < 8) ? ws[lane] : 0;
        t = warp_incl_scan(t, lane);
        if (lane < 8) ws[lane] = t;
    }
    __syncthreads();
    return s + (wid > 0 ? ws[wid - 1] : 0);
}

__global__ __launch_bounds__(256)
void k_scan1(const int* __restrict__ inc, const int* __restrict__ outc, int n,
             int* __restrict__ bsums, float* __restrict__ oq) {
    __shared__ int ws[8];
    int tid = threadIdx.x;
    int i = blockIdx.x * 256 + tid;
    int v = (i < n) ? inc[i] : 0;
    int incl = block_incl_scan(v, tid, ws);
    if (tid == 255) bsums[blockIdx.x] = incl;
    if (i < n) oq[i] = rsqrtf((float)max(outc[i], 1));
}

__global__ __launch_bounds__(256)
void k_scan3(const int* __restrict__ inc, int n, int nb, int E,
             const int* __restrict__ bsums, int* __restrict__ rowp,
             int* __restrict__ cur, float* __restrict__ iq) {
    __shared__ int ws[8];
    __shared__ int soff[256];
    int tid = threadIdx.x;

    int vb = (tid < nb) ? bsums[tid] : 0;
    int inclb = block_incl_scan(vb, tid, ws);
    soff[tid] = inclb - vb;
    __syncthreads();
    int blockoff = soff[blockIdx.x];
    __syncthreads();

    int i = blockIdx.x * 256 + tid;
    int v = (i < n) ? inc[i] : 0;
    int incl = block_incl_scan(v, tid, ws);
    if (i < n) {
        int ex = incl - v + blockoff;
        rowp[i] = ex;
        cur[i] = ex;
        iq[i] = rsqrtf((float)max(v, 1));
    }
    if (blockIdx.x == 0 && tid == 0) rowp[n] = E;
}

// ---------------- CSR fill -----------------------------------------------------
__global__ void k_fill(const int* __restrict__ ei, int E,
                       int* __restrict__ cur, int* __restrict__ csr) {
    int e = blockIdx.x * blockDim.x + threadIdx.x;
    if (e < E) {
        int d = ei[E + e];
        int pos = atomicAdd(&cur[d], 1);
        csr[pos] = ei[e];
    }
}

// ---------------- warp gather of one row: 2 edges/iter, 16 lanes x 16B --------
// After return, lanes 0..15 hold acc[0..7] = summed cols (lane&15)*8 .. +7.
__device__ __forceinline__ void gather_row8(
    const int* __restrict__ csr, int s0, int s1,
    const __half* __restrict__ A, int lane, int col, float acc[8]) {
#pragma unroll
    for (int q = 0; q < 8; q++) acc[q] = 0.0f;
    const unsigned FULL = 0xffffffffu;
    const int half_id = lane >> 4;
    for (int base = s0; base < s1; base += 32) {
        int cnt = min(32, s1 - base);
        int myidx = (lane < cnt) ? csr[base + lane] : 0;
        int t = 0;
        for (; t + 8 <= cnt; t += 8) {
            uint4 r[4];
#pragma unroll
            for (int u = 0; u < 4; u++) {
                int e = t + 2 * u + half_id;
                int s = __shfl_sync(FULL, myidx, e);
                r[u] = *(const uint4*)(A + (size_t)s * D + col);
            }
#pragma unroll
            for (int u = 0; u < 4; u++) {
                float2 f0 = __half22float2(*(__half2*)&r[u].x);
                float2 f1 = __half22float2(*(__half2*)&r[u].y);
                float2 f2 = __half22float2(*(__half2*)&r[u].z);
                float2 f3 = __half22float2(*(__half2*)&r[u].w);
                acc[0] += f0.x; acc[1] += f0.y; acc[2] += f1.x; acc[3] += f1.y;
                acc[4] += f2.x; acc[5] += f2.y; acc[6] += f3.x; acc[7] += f3.y;
            }
        }
        for (; t < cnt; t += 2) {
            int e = t + half_id;
            int s = __shfl_sync(FULL, myidx, e & 31);
            uint4 r = make_uint4(0u, 0u, 0u, 0u);
            if (e < cnt) r = *(const uint4*)(A + (size_t)s * D + col);
            float2 f0 = __half22float2(*(__half2*)&r.x);
            float2 f1 = __half22float2(*(__half2*)&r.y);
            float2 f2 = __half22float2(*(__half2*)&r.z);
            float2 f3 = __half22float2(*(__half2*)&r.w);
            acc[0] += f0.x; acc[1] += f0.y; acc[2] += f1.x; acc[3] += f1.y;
            acc[4] += f2.x; acc[5] += f2.y; acc[6] += f3.x; acc[7] += f3.y;
        }
    }
#pragma unroll
    for (int q = 0; q < 8; q++)
        acc[q] += __shfl_down_sync(FULL, acc[q], 16);
}

// ---------------- MMA helper ----------------------------------------------------
__device__ __forceinline__ void mma16816(float* c, const unsigned* a,
                                         unsigned b0, unsigned b1) {
    asm volatile(
        "mma.sync.aligned.m16n8k16.row.col.f32.f16.f16.f32 "
        "{%0,%1,%2,%3}, {%4,%5,%6,%7}, {%8,%9}, {%0,%1,%2,%3};"
        : "+f"(c[0]), "+f"(c[1]), "+f"(c[2]), "+f"(c[3])
        : "r"(a[0]), "r"(a[1]), "r"(a[2]), "r"(a[3]), "r"(b0), "r"(b1));
}

#define LDA 136   // padded smem stride in halves (272B, 16B-divisible)

// ---------------- common MMA phase (As vs smem-resident Whi/Wlo) ---------------
__device__ __forceinline__ void mma_phase(
    const __half* As, const __half* Bh, const __half* Bl,
    __half* __restrict__ Cm, int rowBase, int nrows,
    int wr, int wc, int g, int tg) {
    float acc[2][8][4];
#pragma unroll
    for (int mt = 0; mt < 2; mt++)
#pragma unroll
        for (int nt = 0; nt < 8; nt++)
#pragma unroll
            for (int q = 0; q < 4; q++) acc[mt][nt][q] = 0.0f;

#pragma unroll
    for (int ks = 0; ks < 8; ks++) {
        const int k0 = ks * 16;
        unsigned a[2][4];
#pragma unroll
        for (int mt = 0; mt < 2; mt++) {
            const __half* pr = As + (wr * 32 + mt * 16 + g) * LDA + k0 + tg * 2;
            a[mt][0] = *(const unsigned*)(pr);
            a[mt][1] = *(const unsigned*)(pr + 8 * LDA);
            a[mt][2] = *(const unsigned*)(pr + 8);
            a[mt][3] = *(const unsigned*)(pr + 8 * LDA + 8);
        }
#pragma unroll
        for (int nt = 0; nt < 8; nt++) {
            const int n = wc * 64 + nt * 8 + g;
            const __half* ph = Bh + n * LDA + k0 + tg * 2;
            const __half* pl = Bl + n * LDA + k0 + tg * 2;
            unsigned bh0 = *(const unsigned*)(ph);
            unsigned bh1 = *(const unsigned*)(ph + 8);
            unsigned bl0 = *(const unsigned*)(pl);
            unsigned bl1 = *(const unsigned*)(pl + 8);
#pragma unroll
            for (int mt = 0; mt < 2; mt++) {
                mma16816(acc[mt][nt], a[mt], bh0, bh1);
                mma16816(acc[mt][nt], a[mt], bl0, bl1);
            }
        }
    }

#pragma unroll
    for (int mt = 0; mt < 2; mt++) {
        int r0 = rowBase + wr * 32 + mt * 16 + g;
        int r1 = r0 + 8;
#pragma unroll
        for (int nt = 0; nt < 8; nt++) {
            int col = wc * 64 + nt * 8 + tg * 2;
            if (r0 < nrows)
                *(__half2*)(Cm + (size_t)r0 * D + col) =
                    __floats2half2_rn(acc[mt][nt][0], acc[mt][nt][1]);
            if (r1 < nrows)
                *(__half2*)(Cm + (size_t)r1 * D + col) =
                    __floats2half2_rn(acc[mt][nt][2], acc[mt][nt][3]);
        }
    }
}

// ---------------- layer-1 GEMM: fp32 A converted+scaled in smem load -----------
__global__ __launch_bounds__(256)
void k_gemm_tc(const float* __restrict__ A, const float* __restrict__ rs,
               const __half* __restrict__ Whi, const __half* __restrict__ Wlo,
               __half* __restrict__ Cm, int nrows, int ntiles) {
    extern __shared__ __half sm[];
    __half* As = sm;
    __half* Bh = sm + 128 * LDA;
    __half* Bl = Bh + 128 * LDA;

    const int tid = threadIdx.x;
    const int wid = tid >> 5, lane = tid & 31;
    const int wr = wid >> 1, wc = wid & 1;
    const int g = lane >> 2, tg = lane & 3;

    for (int j = tid; j < 2048; j += 256) {
        int n = j >> 4, kc = (j & 15) * 8;
        *(uint4*)(Bh + n * LDA + kc) = *(const uint4*)(Whi + n * D + kc);
        *(uint4*)(Bl + n * LDA + kc) = *(const uint4*)(Wlo + n * D + kc);
    }

    for (int tile = blockIdx.x; tile < ntiles; tile += gridDim.x) {
        const int rowBase = tile * 128;
        __syncthreads();
        for (int j = tid; j < 4096; j += 256) {
            int r = j >> 5, kc = (j & 31) * 4;
            int gr = rowBase + r;
            __half2 o[2];
            if (gr < nrows) {
                float s = rs[gr];
                float4 v = *(const float4*)(A + (size_t)gr * D + kc);
                o[0] = __floats2half2_rn(v.x * s, v.y * s);
                o[1] = __floats2half2_rn(v.z * s, v.w * s);
            } else {
                o[0] = __half2half2(__float2half(0.f));
                o[1] = o[0];
            }
            *(uint2*)(As + r * LDA + kc) = *(uint2*)o;
        }
        __syncthreads();
        mma_phase(As, Bh, Bl, Cm, rowBase, nrows, wr, wc, g, tg);
    }
}

// ---------------- fused SpMM + GEMM (layer 2 front half) -----------------------
// Phase 1: gather tile's dst rows from Ain via CSR, apply isq+b+relu+oq, -> As.
// Phase 2: As @ (Whi+Wlo) -> Cm.
__global__ __launch_bounds__(256)
void k_sgemm(const int* __restrict__ csr, const int* __restrict__ rowp,
             const __half* __restrict__ Ain, const float* __restrict__ isq,
             const float* __restrict__ b, const float* __restrict__ oq,
             const __half* __restrict__ Whi, const __half* __restrict__ Wlo,
             __half* __restrict__ Cm, int nrows, int ntiles) {
    extern __shared__ __half sm[];
    __half* As = sm;
    __half* Bh = sm + 128 * LDA;
    __half* Bl = Bh + 128 * LDA;

    const int tid = threadIdx.x;
    const int wid = tid >> 5, lane = tid & 31;
    const int wr = wid >> 1, wc = wid & 1;
    const int g = lane >> 2, tg = lane & 3;
    const int colg = (lane & 15) * 8;

    for (int j = tid; j < 2048; j += 256) {
        int n = j >> 4, kc = (j & 15) * 8;
        *(uint4*)(Bh + n * LDA + kc) = *(const uint4*)(Whi + n * D + kc);
        *(uint4*)(Bl + n * LDA + kc) = *(const uint4*)(Wlo + n * D + kc);
    }

    // per-lane bias slice (fixed columns)
    float4 bv0 = *(const float4*)(b + colg);
    float4 bv1 = *(const float4*)(b + colg + 4);

    for (int tile = blockIdx.x; tile < ntiles; tile += gridDim.x) {
        const int rowBase = tile * 128;
        __syncthreads();

        // phase 1: each warp gathers 16 rows
        for (int rr = 0; rr < 16; rr++) {
            int r = wid * 16 + rr;
            int w = rowBase + r;
            if (w < nrows) {
                float acc[8];
                gather_row8(csr, rowp[w], rowp[w + 1], Ain, lane, colg, acc);
                if (lane < 16) {
                    float sc = isq[w];
                    float post = oq[w];
                    __half2 h[4];
                    h[0] = __floats2half2_rn(
                        fmaxf(fmaf(acc[0], sc, bv0.x), 0.f) * post,
                        fmaxf(fmaf(acc[1], sc, bv0.y), 0.f) * post);
                    h[1] = __floats2half2_rn(
                        fmaxf(fmaf(acc[2], sc, bv0.z), 0.f) * post,
                        fmaxf(fmaf(acc[3], sc, bv0.w), 0.f) * post);
                    h[2] = __floats2half2_rn(
                        fmaxf(fmaf(acc[4], sc, bv1.x), 0.f) * post,
                        fmaxf(fmaf(acc[5], sc, bv1.y), 0.f) * post);
                    h[3] = __floats2half2_rn(
                        fmaxf(fmaf(acc[6], sc, bv1.z), 0.f) * post,
                        fmaxf(fmaf(acc[7], sc, bv1.w), 0.f) * post);
                    *(uint4*)(As + r * LDA + colg) = *(uint4*)h;
                }
            } else if (lane < 16) {
                uint4 z = make_uint4(0u, 0u, 0u, 0u);
                *(uint4*)(As + r * LDA + colg) = z;
            }
        }
        __syncthreads();

        mma_phase(As, Bh, Bl, Cm, rowBase, nrows, wr, wc, g, tg);
    }
}

// ---------------- gather + pool (layer 2 back half; no global h2 store) -------
__global__ __launch_bounds__(256)
void k_gather_pool(const int* __restrict__ csr, const int* __restrict__ rowp,
                   const __half* __restrict__ A, const float* __restrict__ isq,
                   const float* __restrict__ b, const int* __restrict__ n2g,
                   int n) {
    __shared__ float sacc[G * D];
    for (int j = threadIdx.x; j < G * D; j += 256) sacc[j] = 0.0f;
    __syncthreads();

    int w = (blockIdx.x * 256 + threadIdx.x) >> 5;
    int lane = threadIdx.x & 31;
    int col = (lane & 15) * 8;

    if (w < n) {
        float acc[8];
        gather_row8(csr, rowp[w], rowp[w + 1], A, lane, col, acc);
        if (lane < 16) {
            float sc = isq[w];
            float4 bv0 = *(const float4*)(b + col);
            float4 bv1 = *(const float4*)(b + col + 4);
            float v[8];
            v[0] = fmaxf(fmaf(acc[0], sc, bv0.x), 0.f);
            v[1] = fmaxf(fmaf(acc[1], sc, bv0.y), 0.f);
            v[2] = fmaxf(fmaf(acc[2], sc, bv0.z), 0.f);
            v[3] = fmaxf(fmaf(acc[3], sc, bv0.w), 0.f);
            v[4] = fmaxf(fmaf(acc[4], sc, bv1.x), 0.f);
            v[5] = fmaxf(fmaf(acc[5], sc, bv1.y), 0.f);
            v[6] = fmaxf(fmaf(acc[6], sc, bv1.z), 0.f);
            v[7] = fmaxf(fmaf(acc[7], sc, bv1.w), 0.f);
            int gbase = n2g[w] * D + col;
#pragma unroll
            for (int q = 0; q < 8; q++) atomicAdd(&sacc[gbase + q], v[q]);
        }
    }

    __syncthreads();
    for (int j = threadIdx.x; j < G * D; j += 256) {
        float vv = sacc[j];
        if (vv != 0.0f) atomicAdd(&g_sums[j], vv);
    }
}

// ---------------- final: counts via binary search, mean -> linear -> softmax --
__global__ __launch_bounds__(128)
void k_final(const float* __restrict__ Wl, const float* __restrict__ bl,
             const int* __restrict__ n2g, int n, float* __restrict__ out) {
    __shared__ float hg[G * D];
    __shared__ float logits[G * C];
    __shared__ float scnt[G];
    int tid = threadIdx.x;
    if (tid < G) {
        int lo = 0, hi = n;
        while (lo < hi) { int m = (lo + hi) >> 1; if (n2g[m] < tid) lo = m + 1; else hi = m; }
        int lo2 = lo, hi2 = n;
        while (lo2 < hi2) { int m = (lo2 + hi2) >> 1; if (n2g[m] < tid + 1) lo2 = m + 1; else hi2 = m; }
        scnt[tid] = fmaxf((float)(lo2 - lo), 1.0f);
    }
    __syncthreads();
#pragma unroll
    for (int g = 0; g < G; g++)
        hg[g * D + tid] = g_sums[g * D + tid] / scnt[g];
    __syncthreads();
    if (tid < G * C) {
        int g = tid / C, c = tid % C;
        float acc = bl[c];
        for (int k = 0; k < D; k++) acc = fmaf(hg[g * D + k], Wl[k * C + c], acc);
        logits[tid] = acc;
    }
    __syncthreads();
    if (tid < G) {
        float m = -1e30f;
        for (int c = 0; c < C; c++) m = fmaxf(m, logits[tid * C + c]);
        float s = 0.0f;
        float e[C];
        for (int c = 0; c < C; c++) { e[c] = expf(logits[tid * C + c] - m); s += e[c]; }
        float inv = 1.0f / s;
        for (int c = 0; c < C; c++) out[tid * C + c] = e[c] * inv;
    }
}

// ---------------- launch --------------------------------------------------------
extern "C" void kernel_launch(void* const* d_in, const int* in_sizes, int n_in,
                              void* d_out, int out_size) {
    const float* x   = (const float*)d_in[0];
    const int*   ei  = (const int*)d_in[1];
    const int*   n2g = (const int*)d_in[2];
    const float* W1  = (const float*)d_in[3];
    const float* b1  = (const float*)d_in[4];
    const float* W2  = (const float*)d_in[5];
    const float* b2  = (const float*)d_in[6];
    const float* Wl  = (const float*)d_in[7];
    const float* bl  = (const float*)d_in[8];
    float* out = (float*)d_out;

    const int N = in_sizes[2];
    const int E = in_sizes[1] / 2;

    float* outq = nullptr; cudaGetSymbolAddress((void**)&outq, g_out_isqrt);
    float* inq  = nullptr; cudaGetSymbolAddress((void**)&inq,  g_in_isqrt);
    __half* hA  = nullptr; cudaGetSymbolAddress((void**)&hA, g_h16A);
    __half* hB  = nullptr; cudaGetSymbolAddress((void**)&hB, g_h16B);
    __half* w1h = nullptr; cudaGetSymbolAddress((void**)&w1h, g_W1hi);
    __half* w1l = nullptr; cudaGetSymbolAddress((void**)&w1l, g_W1lo);
    __half* w2h = nullptr; cudaGetSymbolAddress((void**)&w2h, g_W2hi);
    __half* w2l = nullptr; cudaGetSymbolAddress((void**)&w2l, g_W2lo);
    float* sums = nullptr; cudaGetSymbolAddress((void**)&sums, g_sums);
    int* outc = nullptr; cudaGetSymbolAddress((void**)&outc, g_outcnt);
    int* inc  = nullptr; cudaGetSymbolAddress((void**)&inc,  g_incnt);
    int* rowp = nullptr; cudaGetSymbolAddress((void**)&rowp, g_rowptr);
    int* cur  = nullptr; cudaGetSymbolAddress((void**)&cur,  g_cursor);
    int* csr  = nullptr; cudaGetSymbolAddress((void**)&csr,  g_csr);
    int* bsum = nullptr; cudaGetSymbolAddress((void**)&bsum, g_bsums);

    const int nb = (N + 255) / 256;
    const int ntiles = (N + 127) / 128;
    const int gemmBlocks = 296;
    const int gatherBlocks = (N * 32 + 255) / 256;
    const int smemGemm = 3 * 128 * LDA * (int)sizeof(__half);

    static cudaStream_t s1;
    static cudaEvent_t ev_fork, ev_csr;
    static int s_init = 0;
    if (!s_init) {
        cudaFuncSetAttribute(k_gemm_tc,
                             cudaFuncAttributeMaxDynamicSharedMemorySize, smemGemm);
        cudaFuncSetAttribute(k_sgemm,
                             cudaFuncAttributeMaxDynamicSharedMemorySize, smemGemm);
        cudaStreamCreateWithFlags(&s1, cudaStreamNonBlocking);
        cudaEventCreateWithFlags(&ev_fork, cudaEventDisableTiming);
        cudaEventCreateWithFlags(&ev_csr, cudaEventDisableTiming);
        s_init = 1;
    }

    // 0..2: setup, degrees, scan1 (+out_isqrt)
    k_setup<<<nb, 256>>>(outc, inc, N, sums, W1, W2, w1h, w1l, w2h, w2l);
    k_degcount<<<(E + 255) / 256, 256>>>(ei, E, outc, inc);
    k_scan1<<<nb, 256>>>(inc, outc, N, bsum, outq);

    // fork: CSR finish on s1, layer-1 GEMM on main
    cudaEventRecord(ev_fork, 0);
    cudaStreamWaitEvent(s1, ev_fork, 0);

    k_scan3<<<nb, 256, 0, s1>>>(inc, N, nb, E, bsum, rowp, cur, inq);
    k_fill<<<(E + 255) / 256, 256, 0, s1>>>(ei, E, cur, csr);
    k_gemm_tc<<<gemmBlocks, 256, smemGemm>>>(x, outq, w1h, w1l, hA, N, ntiles);

    cudaEventRecord(ev_csr, s1);
    cudaStreamWaitEvent(0, ev_csr, 0);

    // fused gather1+gemm2, then gather2+pool (no h2 store)
    k_sgemm<<<gemmBlocks, 256, smemGemm>>>(csr, rowp, hA, inq, b1, outq,
                                           w2h, w2l, hB, N, ntiles);
    k_gather_pool<<<gatherBlocks, 256>>>(csr, rowp, hB, inq, b2, n2g, N);

    k_final<<<1, 128>>>(Wl, bl, n2g, N, out);
}

// round 10
// speedup vs baseline: 1.2916x; 1.2916x over previous
#include <cuda_runtime.h>
#include <cuda_fp16.h>

#define NN 50000
#define EE 800000
#define D  128
#define G  8
#define C  10

// ---------------- scratch (static device globals; no allocs allowed) --------
__device__ float  g_in_isqrt[NN];
__device__ __half g_h16A[NN * D];
__device__ __half g_h16B[NN * D];
__device__ __half g_W1hi[D * D];
__device__ __half g_W1lo[D * D];
__device__ __half g_W2hi[D * D];
__device__ __half g_W2lo[D * D];
__device__ float  g_sums[G * D];
__device__ int    g_outcnt[NN];
__device__ int    g_incnt[NN];
__device__ int    g_rowptr[NN + 1];
__device__ int    g_cursor[NN];
__device__ int    g_csr[EE];
__device__ int    g_bsums[256];

// ---------------- setup: zero degree arrays + pool sums, convert weights ------
__global__ __launch_bounds__(256)
void k_setup(int* __restrict__ outc, int* __restrict__ inc, int n,
             float* __restrict__ sums,
             const float* __restrict__ W1, const float* __restrict__ W2,
             __half* __restrict__ w1h, __half* __restrict__ w1l,
             __half* __restrict__ w2h, __half* __restrict__ w2l) {
    int i = blockIdx.x * 256 + threadIdx.x;
    if (i < n) { outc[i] = 0; inc[i] = 0; }
    if (i < G * D) sums[i] = 0.0f;
    if (i < D * D) {
        int k = i >> 7, nn = i & 127;
        float v = W1[i];
        __half hi = __float2half_rn(v);
        w1h[nn * D + k] = hi;
        w1l[nn * D + k] = __float2half_rn(v - __half2float(hi));
        v = W2[i];
        hi = __float2half_rn(v);
        w2h[nn * D + k] = hi;
        w2l[nn * D + k] = __float2half_rn(v - __half2float(hi));
    }
}

// ---------------- degree histograms (int) ------------------------------------
__global__ void k_degcount(const int* __restrict__ ei, int E,
                           int* __restrict__ outc, int* __restrict__ inc) {
    int e = blockIdx.x * blockDim.x + threadIdx.x;
    if (e < E) {
        atomicAdd(&outc[ei[e]], 1);
        atomicAdd(&inc[ei[E + e]], 1);
    }
}

// ---------------- scan helpers -------------------------------------------------
__device__ __forceinline__ int warp_incl_scan(int v, int lane) {
#pragma unroll
    for (int o = 1; o < 32; o <<= 1) {
        int t = __shfl_up_sync(0xffffffffu, v, o);
        if (lane >= o) v += t;
    }
    return v;
}

__device__ __forceinline__ int block_incl_scan(int v, int tid, int* ws) {
    int lane = tid & 31, wid = tid >> 5;
    int s = warp_incl_scan(v, lane);
    if (lane == 31) ws[wid] = s;
    __syncthreads();
    if (wid == 0) {
        int t = (lane < 8) ? ws[lane] : 0;
        t = warp_incl_scan(t, lane);
        if (lane < 8) ws[lane] = t;
    }
    __syncthreads();
    return s + (wid > 0 ? ws[wid - 1] : 0);
}

// pass 1: per-block (256-wide) sums of in-degrees (s1 stream only)
__global__ __launch_bounds__(256)
void k_scan1(const int* __restrict__ inc, int n, int* __restrict__ bsums) {
    __shared__ int ws[8];
    int tid = threadIdx.x;
    int i = blockIdx.x * 256 + tid;
    int v = (i < n) ? inc[i] : 0;
    int incl = block_incl_scan(v, tid, ws);
    if (tid == 255) bsums[blockIdx.x] = incl;
}

// pass 2 (fused): each block re-scans block sums locally, then its tile
__global__ __launch_bounds__(256)
void k_scan3(const int* __restrict__ inc, int n, int nb, int E,
             const int* __restrict__ bsums, int* __restrict__ rowp,
             int* __restrict__ cur, float* __restrict__ iq) {
    __shared__ int ws[8];
    __shared__ int soff[256];
    int tid = threadIdx.x;

    int vb = (tid < nb) ? bsums[tid] : 0;
    int inclb = block_incl_scan(vb, tid, ws);
    soff[tid] = inclb - vb;
    __syncthreads();
    int blockoff = soff[blockIdx.x];
    __syncthreads();

    int i = blockIdx.x * 256 + tid;
    int v = (i < n) ? inc[i] : 0;
    int incl = block_incl_scan(v, tid, ws);
    if (i < n) {
        int ex = incl - v + blockoff;
        rowp[i] = ex;
        cur[i] = ex;
        iq[i] = rsqrtf((float)max(v, 1));
    }
    if (blockIdx.x == 0 && tid == 0) rowp[n] = E;
}

// ---------------- CSR fill -----------------------------------------------------
__global__ void k_fill(const int* __restrict__ ei, int E,
                       int* __restrict__ cur, int* __restrict__ csr) {
    int e = blockIdx.x * blockDim.x + threadIdx.x;
    if (e < E) {
        int d = ei[E + e];
        int pos = atomicAdd(&cur[d], 1);
        csr[pos] = ei[e];
    }
}

// ---------------- MMA helper ----------------------------------------------------
__device__ __forceinline__ void mma16816(float* c, const unsigned* a,
                                         unsigned b0, unsigned b1) {
    asm volatile(
        "mma.sync.aligned.m16n8k16.row.col.f32.f16.f16.f32 "
        "{%0,%1,%2,%3}, {%4,%5,%6,%7}, {%8,%9}, {%0,%1,%2,%3};"
        : "+f"(c[0]), "+f"(c[1]), "+f"(c[2]), "+f"(c[3])
        : "r"(a[0]), "r"(a[1]), "r"(a[2]), "r"(a[3]), "r"(b0), "r"(b1));
}

#define LDA 136   // padded smem stride in halves

// ---------------- common MMA phase ---------------------------------------------
__device__ __forceinline__ void mma_phase(
    const __half* As, const __half* Bh, const __half* Bl,
    __half* __restrict__ Cm, int rowBase, int nrows,
    int wr, int wc, int g, int tg) {
    float acc[2][8][4];
#pragma unroll
    for (int mt = 0; mt < 2; mt++)
#pragma unroll
        for (int nt = 0; nt < 8; nt++)
#pragma unroll
            for (int q = 0; q < 4; q++) acc[mt][nt][q] = 0.0f;

#pragma unroll
    for (int ks = 0; ks < 8; ks++) {
        const int k0 = ks * 16;
        unsigned a[2][4];
#pragma unroll
        for (int mt = 0; mt < 2; mt++) {
            const __half* pr = As + (wr * 32 + mt * 16 + g) * LDA + k0 + tg * 2;
            a[mt][0] = *(const unsigned*)(pr);
            a[mt][1] = *(const unsigned*)(pr + 8 * LDA);
            a[mt][2] = *(const unsigned*)(pr + 8);
            a[mt][3] = *(const unsigned*)(pr + 8 * LDA + 8);
        }
#pragma unroll
        for (int nt = 0; nt < 8; nt++) {
            const int n = wc * 64 + nt * 8 + g;
            const __half* ph = Bh + n * LDA + k0 + tg * 2;
            const __half* pl = Bl + n * LDA + k0 + tg * 2;
            unsigned bh0 = *(const unsigned*)(ph);
            unsigned bh1 = *(const unsigned*)(ph + 8);
            unsigned bl0 = *(const unsigned*)(pl);
            unsigned bl1 = *(const unsigned*)(pl + 8);
#pragma unroll
            for (int mt = 0; mt < 2; mt++) {
                mma16816(acc[mt][nt], a[mt], bh0, bh1);
                mma16816(acc[mt][nt], a[mt], bl0, bl1);
            }
        }
    }

#pragma unroll
    for (int mt = 0; mt < 2; mt++) {
        int r0 = rowBase + wr * 32 + mt * 16 + g;
        int r1 = r0 + 8;
#pragma unroll
        for (int nt = 0; nt < 8; nt++) {
            int col = wc * 64 + nt * 8 + tg * 2;
            if (r0 < nrows)
                *(__half2*)(Cm + (size_t)r0 * D + col) =
                    __floats2half2_rn(acc[mt][nt][0], acc[mt][nt][1]);
            if (r1 < nrows)
                *(__half2*)(Cm + (size_t)r1 * D + col) =
                    __floats2half2_rn(acc[mt][nt][2], acc[mt][nt][3]);
        }
    }
}

// ---------------- layer-1 GEMM: fp32 A scaled by rsqrt(outdeg) inline ----------
__global__ __launch_bounds__(256)
void k_gemm_tc(const float* __restrict__ A, const int* __restrict__ outc,
               const __half* __restrict__ Whi, const __half* __restrict__ Wlo,
               __half* __restrict__ Cm, int nrows, int ntiles) {
    extern __shared__ __half sm[];
    __half* As = sm;
    __half* Bh = sm + 128 * LDA;
    __half* Bl = Bh + 128 * LDA;

    const int tid = threadIdx.x;
    const int wid = tid >> 5, lane = tid & 31;
    const int wr = wid >> 1, wc = wid & 1;
    const int g = lane >> 2, tg = lane & 3;

    for (int j = tid; j < 2048; j += 256) {
        int n = j >> 4, kc = (j & 15) * 8;
        *(uint4*)(Bh + n * LDA + kc) = *(const uint4*)(Whi + n * D + kc);
        *(uint4*)(Bl + n * LDA + kc) = *(const uint4*)(Wlo + n * D + kc);
    }

    for (int tile = blockIdx.x; tile < ntiles; tile += gridDim.x) {
        const int rowBase = tile * 128;
        __syncthreads();
        for (int j = tid; j < 4096; j += 256) {
            int r = j >> 5, kc = (j & 31) * 4;
            int gr = rowBase + r;
            __half2 o[2];
            if (gr < nrows) {
                float s = rsqrtf((float)max(outc[gr], 1));
                float4 v = *(const float4*)(A + (size_t)gr * D + kc);
                o[0] = __floats2half2_rn(v.x * s, v.y * s);
                o[1] = __floats2half2_rn(v.z * s, v.w * s);
            } else {
                o[0] = __half2half2(__float2half(0.f));
                o[1] = o[0];
            }
            *(uint2*)(As + r * LDA + kc) = *(uint2*)o;
        }
        __syncthreads();
        mma_phase(As, Bh, Bl, Cm, rowBase, nrows, wr, wc, g, tg);
    }
}

// ---------------- layer-2 GEMM: fp16 A straight copy ---------------------------
__global__ __launch_bounds__(256)
void k_gemm_tc16(const __half* __restrict__ A,
                 const __half* __restrict__ Whi, const __half* __restrict__ Wlo,
                 __half* __restrict__ Cm, int nrows, int ntiles) {
    extern __shared__ __half sm[];
    __half* As = sm;
    __half* Bh = sm + 128 * LDA;
    __half* Bl = Bh + 128 * LDA;

    const int tid = threadIdx.x;
    const int wid = tid >> 5, lane = tid & 31;
    const int wr = wid >> 1, wc = wid & 1;
    const int g = lane >> 2, tg = lane & 3;

    for (int j = tid; j < 2048; j += 256) {
        int n = j >> 4, kc = (j & 15) * 8;
        *(uint4*)(Bh + n * LDA + kc) = *(const uint4*)(Whi + n * D + kc);
        *(uint4*)(Bl + n * LDA + kc) = *(const uint4*)(Wlo + n * D + kc);
    }

    for (int tile = blockIdx.x; tile < ntiles; tile += gridDim.x) {
        const int rowBase = tile * 128;
        __syncthreads();
        for (int j = tid; j < 2048; j += 256) {
            int r = j >> 4, kc = (j & 15) * 8;
            int gr = rowBase + r;
            uint4 v = make_uint4(0u, 0u, 0u, 0u);
            if (gr < nrows) v = *(const uint4*)(A + (size_t)gr * D + kc);
            *(uint4*)(As + r * LDA + kc) = v;
        }
        __syncthreads();
        mma_phase(As, Bh, Bl, Cm, rowBase, nrows, wr, wc, g, tg);
    }
}

// ---------------- gather + fused epilogue (+ optional fused pooling) ----------
// SCALE_OQ: multiply by rsqrt(outdeg) (feeds next GEMM).
// DO_POOL: accumulate into g_sums, skip the global store entirely.
template <int SCALE_OQ, int DO_POOL>
__global__ __launch_bounds__(256)
void k_gather(const int* __restrict__ csr, const int* __restrict__ rowp,
              const __half* __restrict__ A, const float* __restrict__ isq,
              const float* __restrict__ b, const int* __restrict__ outc,
              __half* __restrict__ out, int n, const int* __restrict__ n2g) {
    __shared__ float sacc[DO_POOL ? G * D : 1];
    if (DO_POOL) {
        for (int j = threadIdx.x; j < G * D; j += 256) sacc[j] = 0.0f;
        __syncthreads();
    }

    int w = (blockIdx.x * blockDim.x + threadIdx.x) >> 5;
    int lane = threadIdx.x & 31;
    int col = lane * 4;

    if (w < n) {
        int s0 = rowp[w], s1 = rowp[w + 1];
        float4 acc = make_float4(0.f, 0.f, 0.f, 0.f);
        const unsigned FULL = 0xffffffffu;

        for (int base = s0; base < s1; base += 32) {
            int cnt = min(32, s1 - base);
            int myidx = (lane < cnt) ? csr[base + lane] : 0;
            int t = 0;
            for (; t + 8 <= cnt; t += 8) {
                uint2 r[8];
#pragma unroll
                for (int u = 0; u < 8; u++) {
                    int s = __shfl_sync(FULL, myidx, t + u);
                    r[u] = *(const uint2*)(A + (size_t)s * D + col);
                }
#pragma unroll
                for (int u = 0; u < 8; u++) {
                    float2 a = __half22float2(*(__half2*)&r[u].x);
                    float2 bb = __half22float2(*(__half2*)&r[u].y);
                    acc.x += a.x; acc.y += a.y; acc.z += bb.x; acc.w += bb.y;
                }
            }
            for (; t < cnt; t++) {
                int s = __shfl_sync(FULL, myidx, t);
                uint2 r = *(const uint2*)(A + (size_t)s * D + col);
                float2 a = __half22float2(*(__half2*)&r.x);
                float2 bb = __half22float2(*(__half2*)&r.y);
                acc.x += a.x; acc.y += a.y; acc.z += bb.x; acc.w += bb.y;
            }
        }

        float sc = isq[w];
        float post = SCALE_OQ ? rsqrtf((float)max(outc[w], 1)) : 1.0f;
        float4 bb = *(const float4*)(b + col);
        float2 r0, r1;
        r0.x = fmaxf(fmaf(acc.x, sc, bb.x), 0.0f) * post;
        r0.y = fmaxf(fmaf(acc.y, sc, bb.y), 0.0f) * post;
        r1.x = fmaxf(fmaf(acc.z, sc, bb.z), 0.0f) * post;
        r1.y = fmaxf(fmaf(acc.w, sc, bb.w), 0.0f) * post;

        if (!DO_POOL) {
            __half2 o[2] = {__float22half2_rn(r0), __float22half2_rn(r1)};
            *(uint2*)(out + (size_t)w * D + col) = *(uint2*)o;
        } else {
            int gidx = n2g[w] * D + col;
            atomicAdd(&sacc[gidx + 0], r0.x);
            atomicAdd(&sacc[gidx + 1], r0.y);
            atomicAdd(&sacc[gidx + 2], r1.x);
            atomicAdd(&sacc[gidx + 3], r1.y);
        }
    }

    if (DO_POOL) {
        __syncthreads();
        for (int j = threadIdx.x; j < G * D; j += 256) {
            float v = sacc[j];
            if (v != 0.0f) atomicAdd(&g_sums[j], v);
        }
    }
}

// ---------------- final: counts via binary search, mean -> linear -> softmax --
__global__ __launch_bounds__(128)
void k_final(const float* __restrict__ Wl, const float* __restrict__ bl,
             const int* __restrict__ n2g, int n, float* __restrict__ out) {
    __shared__ float hg[G * D];
    __shared__ float logits[G * C];
    __shared__ float scnt[G];
    int tid = threadIdx.x;
    if (tid < G) {
        int lo = 0, hi = n;
        while (lo < hi) { int m = (lo + hi) >> 1; if (n2g[m] < tid) lo = m + 1; else hi = m; }
        int lo2 = lo, hi2 = n;
        while (lo2 < hi2) { int m = (lo2 + hi2) >> 1; if (n2g[m] < tid + 1) lo2 = m + 1; else hi2 = m; }
        scnt[tid] = fmaxf((float)(lo2 - lo), 1.0f);
    }
    __syncthreads();
#pragma unroll
    for (int g = 0; g < G; g++)
        hg[g * D + tid] = g_sums[g * D + tid] / scnt[g];
    __syncthreads();
    if (tid < G * C) {
        int g = tid / C, c = tid % C;
        float acc = bl[c];
        for (int k = 0; k < D; k++) acc = fmaf(hg[g * D + k], Wl[k * C + c], acc);
        logits[tid] = acc;
    }
    __syncthreads();
    if (tid < G) {
        float m = -1e30f;
        for (int c = 0; c < C; c++) m = fmaxf(m, logits[tid * C + c]);
        float s = 0.0f;
        float e[C];
        for (int c = 0; c < C; c++) { e[c] = expf(logits[tid * C + c] - m); s += e[c]; }
        float inv = 1.0f / s;
        for (int c = 0; c < C; c++) out[tid * C + c] = e[c] * inv;
    }
}

// ---------------- launch --------------------------------------------------------
extern "C" void kernel_launch(void* const* d_in, const int* in_sizes, int n_in,
                              void* d_out, int out_size) {
    const float* x   = (const float*)d_in[0];
    const int*   ei  = (const int*)d_in[1];
    const int*   n2g = (const int*)d_in[2];
    const float* W1  = (const float*)d_in[3];
    const float* b1  = (const float*)d_in[4];
    const float* W2  = (const float*)d_in[5];
    const float* b2  = (const float*)d_in[6];
    const float* Wl  = (const float*)d_in[7];
    const float* bl  = (const float*)d_in[8];
    float* out = (float*)d_out;

    const int N = in_sizes[2];
    const int E = in_sizes[1] / 2;

    float* inq  = nullptr; cudaGetSymbolAddress((void**)&inq,  g_in_isqrt);
    __half* hA  = nullptr; cudaGetSymbolAddress((void**)&hA, g_h16A);
    __half* hB  = nullptr; cudaGetSymbolAddress((void**)&hB, g_h16B);
    __half* w1h = nullptr; cudaGetSymbolAddress((void**)&w1h, g_W1hi);
    __half* w1l = nullptr; cudaGetSymbolAddress((void**)&w1l, g_W1lo);
    __half* w2h = nullptr; cudaGetSymbolAddress((void**)&w2h, g_W2hi);
    __half* w2l = nullptr; cudaGetSymbolAddress((void**)&w2l, g_W2lo);
    float* sums = nullptr; cudaGetSymbolAddress((void**)&sums, g_sums);
    int* outc = nullptr; cudaGetSymbolAddress((void**)&outc, g_outcnt);
    int* inc  = nullptr; cudaGetSymbolAddress((void**)&inc,  g_incnt);
    int* rowp = nullptr; cudaGetSymbolAddress((void**)&rowp, g_rowptr);
    int* cur  = nullptr; cudaGetSymbolAddress((void**)&cur,  g_cursor);
    int* csr  = nullptr; cudaGetSymbolAddress((void**)&csr,  g_csr);
    int* bsum = nullptr; cudaGetSymbolAddress((void**)&bsum, g_bsums);

    const int nb = (N + 255) / 256;
    const int ntiles = (N + 127) / 128;
    const int gemmBlocks = 296;
    const int gatherBlocks = (N * 32 + 255) / 256;
    const int smemGemm = 3 * 128 * LDA * (int)sizeof(__half);

    static cudaStream_t s1;
    static cudaEvent_t ev_fork, ev_csr;
    static int s_init = 0;
    if (!s_init) {
        cudaFuncSetAttribute(k_gemm_tc,
                             cudaFuncAttributeMaxDynamicSharedMemorySize, smemGemm);
        cudaFuncSetAttribute(k_gemm_tc16,
                             cudaFuncAttributeMaxDynamicSharedMemorySize, smemGemm);
        cudaStreamCreateWithFlags(&s1, cudaStreamNonBlocking);
        cudaEventCreateWithFlags(&ev_fork, cudaEventDisableTiming);
        cudaEventCreateWithFlags(&ev_csr, cudaEventDisableTiming);
        s_init = 1;
    }

    // 0..1: setup, degrees (main)
    k_setup<<<nb, 256>>>(outc, inc, N, sums, W1, W2, w1h, w1l, w2h, w2l);
    k_degcount<<<(E + 255) / 256, 256>>>(ei, E, outc, inc);

    // fork: full CSR build on s1; layer-1 GEMM on main (needs only outc)
    cudaEventRecord(ev_fork, 0);
    cudaStreamWaitEvent(s1, ev_fork, 0);

    k_scan1<<<nb, 256, 0, s1>>>(inc, N, bsum);
    k_scan3<<<nb, 256, 0, s1>>>(inc, N, nb, E, bsum, rowp, cur, inq);
    k_fill<<<(E + 255) / 256, 256, 0, s1>>>(ei, E, cur, csr);

    k_gemm_tc<<<gemmBlocks, 256, smemGemm>>>(x, outc, w1h, w1l, hA, N, ntiles);

    cudaEventRecord(ev_csr, s1);
    cudaStreamWaitEvent(0, ev_csr, 0);

    // gather1 (folds oq), gemm2, gather2 + fused pool (no global store)
    k_gather<1, 0><<<gatherBlocks, 256>>>(csr, rowp, hA, inq, b1, outc, hB, N, n2g);
    k_gemm_tc16<<<gemmBlocks, 256, smemGemm>>>(hB, w2h, w2l, hA, N, ntiles);
    k_gather<0, 1><<<gatherBlocks, 256>>>(csr, rowp, hA, inq, b2, outc, hB, N, n2g);

    k_final<<<1, 128>>>(Wl, bl, n2g, N, out);
}